// round 1
// baseline (speedup 1.0000x reference)
#include <cuda_runtime.h>
#include <cuda_bf16.h>
#include <math.h>

// ---------------------------------------------------------------------------
// MultiLayerGNN: out = L2(L1(x)) + x
//   adj_norm @ v  ==  d ⊙ (adj @ (d ⊙ v)),  d = rsqrt(max(rowsum(adj),1e-6))
//   Li(v) = gelu(LN(adj_norm@v @ Wi^T + bi; gi, betai))
// Shapes: N=8192 nodes, E=H=256.
// ---------------------------------------------------------------------------

#define NNODES 8192
#define FEAT   256

// Scratch (no allocation allowed -> __device__ globals)
__device__ float g_dvec[NNODES];
__device__ float g_bufA[NNODES * FEAT];
__device__ float g_bufB[NNODES * FEAT];

// ---------------------------------------------------------------------------
// Block-wide sum for blockDim.x == 256. All threads return the total.
// ---------------------------------------------------------------------------
__device__ __forceinline__ float block_sum_256(float v, float* sh8) {
    int t = threadIdx.x;
#pragma unroll
    for (int o = 16; o > 0; o >>= 1) v += __shfl_xor_sync(0xffffffffu, v, o);
    if ((t & 31) == 0) sh8[t >> 5] = v;
    __syncthreads();
    float tot = ((sh8[0] + sh8[1]) + (sh8[2] + sh8[3])) +
                ((sh8[4] + sh8[5]) + (sh8[6] + sh8[7]));
    __syncthreads();   // allow sh8 reuse
    return tot;
}

// ---------------------------------------------------------------------------
// K1: d[i] = rsqrt(max(sum_j adj[i,j], 1e-6))     grid=8192, block=256
// ---------------------------------------------------------------------------
__global__ void deg_kernel(const float* __restrict__ adj, float* __restrict__ d) {
    __shared__ float sh8[8];
    int row = blockIdx.x;
    int t = threadIdx.x;
    const float4* p = reinterpret_cast<const float4*>(adj + (size_t)row * NNODES);
    float s = 0.f;
#pragma unroll
    for (int i = 0; i < 8; i++) {
        float4 v = p[t + (i << 8)];
        s += (v.x + v.y) + (v.z + v.w);
    }
    float tot = block_sum_256(s, sh8);
    if (t == 0) d[row] = rsqrtf(fmaxf(tot, 1e-6f));
}

// ---------------------------------------------------------------------------
// K2: out[i, f] = in[i, f] * d[i]      (8192x256 fp32, float4 grid-stride)
// total float4 elems = 8192*256/4 = 524288 ; 64 float4 per row
// ---------------------------------------------------------------------------
__global__ void rowscale_kernel(const float* __restrict__ in,
                                const float* __restrict__ d,
                                float* __restrict__ out) {
    int i = blockIdx.x * blockDim.x + threadIdx.x;
    if (i >= (NNODES * FEAT / 4)) return;
    float sc = d[i >> 6];
    float4 v = reinterpret_cast<const float4*>(in)[i];
    v.x *= sc; v.y *= sc; v.z *= sc; v.w *= sc;
    reinterpret_cast<float4*>(out)[i] = v;
}

// ---------------------------------------------------------------------------
// K3: big GEMM  C[m,n] = dscale[m] * sum_k A[m,k]*B[k,n]
//     A: 8192x8192 (adj, lda=8192), B: 8192x256 (ldb=256), C: 8192x256
//     BM=128 BN=64 BK=16, 128 threads, 8x8 per-thread tile.
//     grid = (N/BN=4, M/BM=64); x fastest so the 4 col-blocks of the same
//     row panel run concurrently and share adj lines through L2.
// ---------------------------------------------------------------------------
__global__ void __launch_bounds__(128)
gemm_big_kernel(const float* __restrict__ A, const float* __restrict__ B,
                const float* __restrict__ dscale, float* __restrict__ C) {
    const int K = NNODES;
    const int N = FEAT;
    __shared__ float As[16][128];
    __shared__ float Bs[16][64];

    int tid = threadIdx.x;
    int br = blockIdx.y << 7;      // *128
    int bc = blockIdx.x << 6;      // *64
    int tm = (tid >> 3) << 3;      // row offset 0..120
    int tn = (tid & 7) << 3;       // col offset 0..56

    float acc[8][8];
#pragma unroll
    for (int i = 0; i < 8; i++)
#pragma unroll
        for (int j = 0; j < 8; j++) acc[i][j] = 0.f;

    for (int k0 = 0; k0 < K; k0 += 16) {
        // load A tile 128x16 (512 float4, 4 per thread), store transposed
#pragma unroll
        for (int i = 0; i < 4; i++) {
            int idx = tid + (i << 7);
            int r = idx >> 2, c = (idx & 3) << 2;
            float4 v = *reinterpret_cast<const float4*>(
                &A[(size_t)(br + r) * K + (k0 + c)]);
            As[c + 0][r] = v.x; As[c + 1][r] = v.y;
            As[c + 2][r] = v.z; As[c + 3][r] = v.w;
        }
        // load B tile 16x64 (256 float4, 2 per thread), direct
#pragma unroll
        for (int i = 0; i < 2; i++) {
            int idx = tid + (i << 7);
            int r = idx >> 4, c = (idx & 15) << 2;
            *reinterpret_cast<float4*>(&Bs[r][c]) =
                *reinterpret_cast<const float4*>(&B[(size_t)(k0 + r) * N + (bc + c)]);
        }
        __syncthreads();
#pragma unroll
        for (int k = 0; k < 16; k++) {
            float a[8], b[8];
            *reinterpret_cast<float4*>(&a[0]) = *reinterpret_cast<float4*>(&As[k][tm]);
            *reinterpret_cast<float4*>(&a[4]) = *reinterpret_cast<float4*>(&As[k][tm + 4]);
            *reinterpret_cast<float4*>(&b[0]) = *reinterpret_cast<float4*>(&Bs[k][tn]);
            *reinterpret_cast<float4*>(&b[4]) = *reinterpret_cast<float4*>(&Bs[k][tn + 4]);
#pragma unroll
            for (int i = 0; i < 8; i++)
#pragma unroll
                for (int j = 0; j < 8; j++) acc[i][j] += a[i] * b[j];
        }
        __syncthreads();
    }

#pragma unroll
    for (int i = 0; i < 8; i++) {
        int row = br + tm + i;
        float sc = dscale[row];
        float4 v0 = make_float4(acc[i][0] * sc, acc[i][1] * sc,
                                acc[i][2] * sc, acc[i][3] * sc);
        float4 v1 = make_float4(acc[i][4] * sc, acc[i][5] * sc,
                                acc[i][6] * sc, acc[i][7] * sc);
        *reinterpret_cast<float4*>(&C[(size_t)row * N + bc + tn]) = v0;
        *reinterpret_cast<float4*>(&C[(size_t)row * N + bc + tn + 4]) = v1;
    }
}

// ---------------------------------------------------------------------------
// K4: small GEMM  C[m,n] = sum_k A[m,k]*W[n,k] + bias[n]
//     A: 8192x256, W: 256x256 (row-major, (out,in)); same tiling as K3.
// ---------------------------------------------------------------------------
__global__ void __launch_bounds__(128)
gemm_nt_bias_kernel(const float* __restrict__ A, const float* __restrict__ W,
                    const float* __restrict__ bias, float* __restrict__ C) {
    const int K = FEAT;
    const int N = FEAT;
    __shared__ float As[16][128];
    __shared__ float Bs[16][64];

    int tid = threadIdx.x;
    int br = blockIdx.y << 7;
    int bc = blockIdx.x << 6;
    int tm = (tid >> 3) << 3;
    int tn = (tid & 7) << 3;

    float acc[8][8];
#pragma unroll
    for (int i = 0; i < 8; i++)
#pragma unroll
        for (int j = 0; j < 8; j++) acc[i][j] = 0.f;

    for (int k0 = 0; k0 < K; k0 += 16) {
#pragma unroll
        for (int i = 0; i < 4; i++) {
            int idx = tid + (i << 7);
            int r = idx >> 2, c = (idx & 3) << 2;
            float4 v = *reinterpret_cast<const float4*>(
                &A[(size_t)(br + r) * K + (k0 + c)]);
            As[c + 0][r] = v.x; As[c + 1][r] = v.y;
            As[c + 2][r] = v.z; As[c + 3][r] = v.w;
        }
        // B tile: Bs[k][n] = W[bc+n][k0+k]; 64 rows x 16 k = 256 float4 (2/thread)
#pragma unroll
        for (int i = 0; i < 2; i++) {
            int idx = tid + (i << 7);
            int n = idx >> 2, c = (idx & 3) << 2;
            float4 v = *reinterpret_cast<const float4*>(
                &W[(size_t)(bc + n) * K + (k0 + c)]);
            Bs[c + 0][n] = v.x; Bs[c + 1][n] = v.y;
            Bs[c + 2][n] = v.z; Bs[c + 3][n] = v.w;
        }
        __syncthreads();
#pragma unroll
        for (int k = 0; k < 16; k++) {
            float a[8], b[8];
            *reinterpret_cast<float4*>(&a[0]) = *reinterpret_cast<float4*>(&As[k][tm]);
            *reinterpret_cast<float4*>(&a[4]) = *reinterpret_cast<float4*>(&As[k][tm + 4]);
            *reinterpret_cast<float4*>(&b[0]) = *reinterpret_cast<float4*>(&Bs[k][tn]);
            *reinterpret_cast<float4*>(&b[4]) = *reinterpret_cast<float4*>(&Bs[k][tn + 4]);
#pragma unroll
            for (int i = 0; i < 8; i++)
#pragma unroll
                for (int j = 0; j < 8; j++) acc[i][j] += a[i] * b[j];
        }
        __syncthreads();
    }

    float bs0[8];
#pragma unroll
    for (int j = 0; j < 8; j++) bs0[j] = bias[bc + tn + j];
#pragma unroll
    for (int i = 0; i < 8; i++) {
        int row = br + tm + i;
        float4 v0 = make_float4(acc[i][0] + bs0[0], acc[i][1] + bs0[1],
                                acc[i][2] + bs0[2], acc[i][3] + bs0[3]);
        float4 v1 = make_float4(acc[i][4] + bs0[4], acc[i][5] + bs0[5],
                                acc[i][6] + bs0[6], acc[i][7] + bs0[7]);
        *reinterpret_cast<float4*>(&C[(size_t)row * FEAT + bc + tn]) = v0;
        *reinterpret_cast<float4*>(&C[(size_t)row * FEAT + bc + tn + 4]) = v1;
    }
}

// ---------------------------------------------------------------------------
// K5: out[row,:] = gelu(LN(Z[row,:]; g, beta)) (+ res[row,:])
//     grid=8192, block=256 (one thread per feature). Exact erf GELU.
// ---------------------------------------------------------------------------
__global__ void ln_gelu_kernel(const float* __restrict__ Z,
                               const float* __restrict__ g,
                               const float* __restrict__ beta,
                               const float* __restrict__ res,
                               float* __restrict__ out) {
    __shared__ float sh8[8];
    int row = blockIdx.x;
    int t = threadIdx.x;
    size_t idx = (size_t)row * FEAT + t;
    float v = Z[idx];
    float mean = block_sum_256(v, sh8) * (1.f / FEAT);
    float dv = v - mean;
    float var = block_sum_256(dv * dv, sh8) * (1.f / FEAT);
    float y = dv * rsqrtf(var + 1e-5f) * g[t] + beta[t];
    float r = 0.5f * y * (1.f + erff(y * 0.70710678118654752f));
    if (res) r += res[idx];
    out[idx] = r;
}

// ---------------------------------------------------------------------------
// Launch: 9 kernels, graph-capturable, allocation-free.
// Input order (metadata): x, adj, W1, b1, g1, beta1, W2, b2, g2, beta2
// ---------------------------------------------------------------------------
extern "C" void kernel_launch(void* const* d_in, const int* in_sizes, int n_in,
                              void* d_out, int out_size) {
    const float* x   = (const float*)d_in[0];
    const float* adj = (const float*)d_in[1];
    const float* W1  = (const float*)d_in[2];
    const float* b1  = (const float*)d_in[3];
    const float* g1  = (const float*)d_in[4];
    const float* be1 = (const float*)d_in[5];
    const float* W2  = (const float*)d_in[6];
    const float* b2  = (const float*)d_in[7];
    const float* g2  = (const float*)d_in[8];
    const float* be2 = (const float*)d_in[9];
    float* out = (float*)d_out;

    float *dvec, *bufA, *bufB;
    cudaGetSymbolAddress((void**)&dvec, g_dvec);
    cudaGetSymbolAddress((void**)&bufA, g_bufA);
    cudaGetSymbolAddress((void**)&bufB, g_bufB);

    dim3 gemm_grid(FEAT / 64, NNODES / 128);   // (4, 64)
    int scale_blocks = (NNODES * FEAT / 4 + 255) / 256;

    // d = rsqrt(max(rowsum(adj), 1e-6))
    deg_kernel<<<NNODES, 256>>>(adj, dvec);

    // ---- layer 1 ----
    rowscale_kernel<<<scale_blocks, 256>>>(x, dvec, bufA);        // xs = d.x
    gemm_big_kernel<<<gemm_grid, 128>>>(adj, bufA, dvec, bufB);   // agg1 = d.(adj@xs)
    gemm_nt_bias_kernel<<<gemm_grid, 128>>>(bufB, W1, b1, bufA);  // z1 = agg1@W1^T + b1
    ln_gelu_kernel<<<NNODES, 256>>>(bufA, g1, be1, nullptr, bufB);// h1 = gelu(LN(z1))

    // ---- layer 2 ----
    rowscale_kernel<<<scale_blocks, 256>>>(bufB, dvec, bufA);     // hs = d.h1
    gemm_big_kernel<<<gemm_grid, 128>>>(adj, bufA, dvec, bufB);   // agg2 = d.(adj@hs)
    gemm_nt_bias_kernel<<<gemm_grid, 128>>>(bufB, W2, b2, bufA);  // z2 = agg2@W2^T + b2
    ln_gelu_kernel<<<NNODES, 256>>>(bufA, g2, be2, x, out);       // out = gelu(LN(z2)) + x
}

// round 4
// speedup vs baseline: 3.6972x; 3.6972x over previous
#include <cuda_runtime.h>
#include <math.h>
#include <stdint.h>

// ---------------------------------------------------------------------------
// MultiLayerGNN: out = L2(L1(x)) + x
//   adj_norm @ v == d ⊙ (adj @ (d ⊙ v)),  d = rsqrt(max(rowsum(adj),1e-6))
// Big GEMMs on mma.sync tf32 (portable sm_80+ tensor path; tcgen05 is not
// available because the harness compiles plain compute_100 PTX).
// ---------------------------------------------------------------------------

#define NNODES 8192
#define FEAT   256

__device__ float g_dvec[NNODES];
__device__ float g_bufA[NNODES * FEAT];   // also holds Bt [256 x 8192]
__device__ float g_bufB[NNODES * FEAT];

// ---------------------------------------------------------------------------
__device__ __forceinline__ uint32_t smem_u32(const void* p) {
    uint32_t a;
    asm("{ .reg .u64 t; cvta.to.shared.u64 t, %1; cvt.u32.u64 %0, t; }"
        : "=r"(a) : "l"(p));
    return a;
}
__device__ __forceinline__ void cp_async16(uint32_t dst, const void* src) {
    asm volatile("cp.async.cg.shared.global [%0], [%1], 16;" :: "r"(dst), "l"(src) : "memory");
}
#define CP_COMMIT()  asm volatile("cp.async.commit_group;" ::: "memory")
#define CP_WAIT(n)   asm volatile("cp.async.wait_group %0;" :: "n"(n) : "memory")

__device__ __forceinline__ void mma_tf32_16x8x8(float* d, const uint32_t* a,
                                                const uint32_t* b) {
    asm volatile(
        "mma.sync.aligned.m16n8k8.row.col.f32.tf32.tf32.f32 "
        "{%0,%1,%2,%3}, {%4,%5,%6,%7}, {%8,%9}, {%0,%1,%2,%3};"
        : "+f"(d[0]), "+f"(d[1]), "+f"(d[2]), "+f"(d[3])
        : "r"(a[0]), "r"(a[1]), "r"(a[2]), "r"(a[3]), "r"(b[0]), "r"(b[1]));
}

// ---------------------------------------------------------------------------
__device__ __forceinline__ float block_sum_256(float v, float* sh8) {
    int t = threadIdx.x;
#pragma unroll
    for (int o = 16; o > 0; o >>= 1) v += __shfl_xor_sync(0xffffffffu, v, o);
    if ((t & 31) == 0) sh8[t >> 5] = v;
    __syncthreads();
    float tot = ((sh8[0] + sh8[1]) + (sh8[2] + sh8[3])) +
                ((sh8[4] + sh8[5]) + (sh8[6] + sh8[7]));
    __syncthreads();
    return tot;
}

// ---------------------------------------------------------------------------
// K1: d[i] = rsqrt(max(rowsum(adj), 1e-6))
// ---------------------------------------------------------------------------
__global__ void deg_kernel(const float* __restrict__ adj, float* __restrict__ d) {
    __shared__ float sh8[8];
    int row = blockIdx.x;
    int t = threadIdx.x;
    const float4* p = reinterpret_cast<const float4*>(adj + (size_t)row * NNODES);
    float s = 0.f;
#pragma unroll
    for (int i = 0; i < 8; i++) {
        float4 v = p[t + (i << 8)];
        s += (v.x + v.y) + (v.z + v.w);
    }
    float tot = block_sum_256(s, sh8);
    if (t == 0) d[row] = rsqrtf(fmaxf(tot, 1e-6f));
}

// ---------------------------------------------------------------------------
// K2: Bt[n, k] = d[k] * in[k, n]   ([8192,256] -> [256,8192])
// ---------------------------------------------------------------------------
__global__ void transpose_scale_kernel(const float* __restrict__ in,
                                       const float* __restrict__ d,
                                       float* __restrict__ out) {
    __shared__ float tile[32][33];
    int n0 = blockIdx.x * 32, k0 = blockIdx.y * 32;
    int tx = threadIdx.x, ty = threadIdx.y;
#pragma unroll
    for (int j = 0; j < 32; j += 8) {
        int k = k0 + ty + j;
        tile[ty + j][tx] = in[(size_t)k * FEAT + n0 + tx] * d[k];
    }
    __syncthreads();
#pragma unroll
    for (int j = 0; j < 32; j += 8) {
        int n = n0 + ty + j;
        out[(size_t)n * NNODES + k0 + tx] = tile[tx][ty + j];
    }
}

// ---------------------------------------------------------------------------
// K3: big GEMM on mma.sync tf32.
//   C[m,n] = dscale[m] * sum_k A[m,k] * Bt[n,k]
//   A: adj [8192 x 8192] row-major; Bt: [256 x 8192] row-major (= col-major B).
//   BM=128 BN=128 BK=32; 128 threads = 4 warps (2x2), warp tile 64x64.
//   SMEM rows padded to 36 floats: fragment pattern (4r+c) is conflict-free.
//   3-stage cp.async pipeline. Grid (2, 64) = 128 CTAs, one wave.
// ---------------------------------------------------------------------------
#define BK 32
#define ROWF 36                       // padded row stride (floats)
#define ROWB (ROWF * 4)               // 144 bytes
#define STG_F (128 * ROWF * 2)        // floats per stage (A+B) = 9216
#define STG_B (STG_F * 4)             // 36864 bytes
#define B_OFF_F (128 * ROWF)          // 4608
#define NSTAGE 3
#define NITER (NNODES / BK)           // 256
#define GEMM_SMEM (NSTAGE * STG_B)    // 110592

__device__ __forceinline__ void load_stage(uint32_t sb, int s, int k0,
                                           const float* A, const float* Bt,
                                           int br, int bc, int tid) {
    uint32_t ab = sb + s * STG_B;
    uint32_t bb = ab + B_OFF_F * 4;
#pragma unroll
    for (int j = 0; j < 8; j++) {
        int idx = tid + (j << 7);     // 0..1023
        int r = idx >> 3;             // 0..127
        int cs = (idx & 7) << 4;      // byte col 0..112
        cp_async16(ab + r * ROWB + cs,
                   (const char*)(A + (size_t)(br + r) * NNODES + k0) + cs);
    }
#pragma unroll
    for (int j = 0; j < 8; j++) {
        int idx = tid + (j << 7);
        int r = idx >> 3;
        int cs = (idx & 7) << 4;
        cp_async16(bb + r * ROWB + cs,
                   (const char*)(Bt + (size_t)(bc + r) * NNODES + k0) + cs);
    }
}

__global__ void __launch_bounds__(128, 1)
gemm_tf32_kernel(const float* __restrict__ A, const float* __restrict__ Bt,
                 const float* __restrict__ dscale, float* __restrict__ C) {
    extern __shared__ float smem_f[];
    uint32_t sb = smem_u32(smem_f);
    int tid = threadIdx.x;
    int wid = tid >> 5, lane = tid & 31;
    int r = lane >> 2, c = lane & 3;
    int wm = (wid & 1) << 6;          // warp row offset 0/64
    int wn = (wid >> 1) << 6;         // warp col offset 0/64
    int br = blockIdx.y << 7, bc = blockIdx.x << 7;

    float acc[4][8][4];
#pragma unroll
    for (int i = 0; i < 4; i++)
#pragma unroll
        for (int j = 0; j < 8; j++)
#pragma unroll
            for (int q = 0; q < 4; q++) acc[i][j][q] = 0.f;

#pragma unroll
    for (int s = 0; s < NSTAGE; s++) {
        load_stage(sb, s, s * BK, A, Bt, br, bc, tid);
        CP_COMMIT();
    }

    int stage = 0;
    for (int it = 0; it < NITER; it++) {
        CP_WAIT(NSTAGE - 1);
        __syncthreads();

        const float* As = smem_f + stage * STG_F;
        const float* Bs = As + B_OFF_F;
#pragma unroll
        for (int kk = 0; kk < 4; kk++) {
            int kc = (kk << 3) + c;
            uint32_t a[4][4], b[8][2];
#pragma unroll
            for (int i = 0; i < 4; i++) {
                int row = wm + (i << 4) + r;
                a[i][0] = __float_as_uint(As[row * ROWF + kc]);
                a[i][1] = __float_as_uint(As[(row + 8) * ROWF + kc]);
                a[i][2] = __float_as_uint(As[row * ROWF + kc + 4]);
                a[i][3] = __float_as_uint(As[(row + 8) * ROWF + kc + 4]);
            }
#pragma unroll
            for (int j = 0; j < 8; j++) {
                int col = wn + (j << 3) + r;
                b[j][0] = __float_as_uint(Bs[col * ROWF + kc]);
                b[j][1] = __float_as_uint(Bs[col * ROWF + kc + 4]);
            }
#pragma unroll
            for (int i = 0; i < 4; i++)
#pragma unroll
                for (int j = 0; j < 8; j++)
                    mma_tf32_16x8x8(acc[i][j], a[i], b[j]);
        }
        __syncthreads();

        int nk = it + NSTAGE;
        if (nk < NITER) load_stage(sb, stage, nk * BK, A, Bt, br, bc, tid);
        CP_COMMIT();
        if (++stage == NSTAGE) stage = 0;
    }

    // epilogue: acc rows (wm+i*16+r, +8), cols (wn+j*8+2c, +1)
#pragma unroll
    for (int i = 0; i < 4; i++) {
        int row0 = br + wm + (i << 4) + r;
        float sc0 = dscale[row0];
        float sc8 = dscale[row0 + 8];
        float* p0 = C + (size_t)row0 * FEAT + bc + wn + (c << 1);
        float* p8 = C + (size_t)(row0 + 8) * FEAT + bc + wn + (c << 1);
#pragma unroll
        for (int j = 0; j < 8; j++) {
            float2 v0 = make_float2(acc[i][j][0] * sc0, acc[i][j][1] * sc0);
            float2 v8 = make_float2(acc[i][j][2] * sc8, acc[i][j][3] * sc8);
            *reinterpret_cast<float2*>(p0 + (j << 3)) = v0;
            *reinterpret_cast<float2*>(p8 + (j << 3)) = v8;
        }
    }
}

// ---------------------------------------------------------------------------
// K4: small GEMM  C[m,n] = sum_k A[m,k]*W[n,k] + bias[n]   (SIMT fp32)
// ---------------------------------------------------------------------------
__global__ void __launch_bounds__(128)
gemm_nt_bias_kernel(const float* __restrict__ A, const float* __restrict__ W,
                    const float* __restrict__ bias, float* __restrict__ C) {
    const int K = FEAT;
    __shared__ float As[16][128];
    __shared__ float Bs[16][64];

    int tid = threadIdx.x;
    int br = blockIdx.y << 7;
    int bc = blockIdx.x << 6;
    int tm = (tid >> 3) << 3;
    int tn = (tid & 7) << 3;

    float acc[8][8];
#pragma unroll
    for (int i = 0; i < 8; i++)
#pragma unroll
        for (int j = 0; j < 8; j++) acc[i][j] = 0.f;

    for (int k0 = 0; k0 < K; k0 += 16) {
#pragma unroll
        for (int i = 0; i < 4; i++) {
            int idx = tid + (i << 7);
            int rr = idx >> 2, cc = (idx & 3) << 2;
            float4 v = *reinterpret_cast<const float4*>(
                &A[(size_t)(br + rr) * K + (k0 + cc)]);
            As[cc + 0][rr] = v.x; As[cc + 1][rr] = v.y;
            As[cc + 2][rr] = v.z; As[cc + 3][rr] = v.w;
        }
#pragma unroll
        for (int i = 0; i < 2; i++) {
            int idx = tid + (i << 7);
            int n = idx >> 2, cc = (idx & 3) << 2;
            float4 v = *reinterpret_cast<const float4*>(
                &W[(size_t)(bc + n) * K + (k0 + cc)]);
            Bs[cc + 0][n] = v.x; Bs[cc + 1][n] = v.y;
            Bs[cc + 2][n] = v.z; Bs[cc + 3][n] = v.w;
        }
        __syncthreads();
#pragma unroll
        for (int k = 0; k < 16; k++) {
            float a[8], b[8];
            *reinterpret_cast<float4*>(&a[0]) = *reinterpret_cast<float4*>(&As[k][tm]);
            *reinterpret_cast<float4*>(&a[4]) = *reinterpret_cast<float4*>(&As[k][tm + 4]);
            *reinterpret_cast<float4*>(&b[0]) = *reinterpret_cast<float4*>(&Bs[k][tn]);
            *reinterpret_cast<float4*>(&b[4]) = *reinterpret_cast<float4*>(&Bs[k][tn + 4]);
#pragma unroll
            for (int i = 0; i < 8; i++)
#pragma unroll
                for (int j = 0; j < 8; j++) acc[i][j] += a[i] * b[j];
        }
        __syncthreads();
    }

    float bs0[8];
#pragma unroll
    for (int j = 0; j < 8; j++) bs0[j] = bias[bc + tn + j];
#pragma unroll
    for (int i = 0; i < 8; i++) {
        int row = br + tm + i;
        float4 v0 = make_float4(acc[i][0] + bs0[0], acc[i][1] + bs0[1],
                                acc[i][2] + bs0[2], acc[i][3] + bs0[3]);
        float4 v1 = make_float4(acc[i][4] + bs0[4], acc[i][5] + bs0[5],
                                acc[i][6] + bs0[6], acc[i][7] + bs0[7]);
        *reinterpret_cast<float4*>(&C[(size_t)row * FEAT + bc + tn]) = v0;
        *reinterpret_cast<float4*>(&C[(size_t)row * FEAT + bc + tn + 4]) = v1;
    }
}

// ---------------------------------------------------------------------------
// K5: out = gelu(LN(Z)) (+res)
// ---------------------------------------------------------------------------
__global__ void ln_gelu_kernel(const float* __restrict__ Z,
                               const float* __restrict__ g,
                               const float* __restrict__ beta,
                               const float* __restrict__ res,
                               float* __restrict__ out) {
    __shared__ float sh8[8];
    int row = blockIdx.x;
    int t = threadIdx.x;
    size_t idx = (size_t)row * FEAT + t;
    float v = Z[idx];
    float mean = block_sum_256(v, sh8) * (1.f / FEAT);
    float dv = v - mean;
    float var = block_sum_256(dv * dv, sh8) * (1.f / FEAT);
    float y = dv * rsqrtf(var + 1e-5f) * g[t] + beta[t];
    float rr = 0.5f * y * (1.f + erff(y * 0.70710678118654752f));
    if (res) rr += res[idx];
    out[idx] = rr;
}

// ---------------------------------------------------------------------------
// Launch: 9 kernels, graph-capturable, allocation-free.
// ---------------------------------------------------------------------------
extern "C" void kernel_launch(void* const* d_in, const int* in_sizes, int n_in,
                              void* d_out, int out_size) {
    const float* x   = (const float*)d_in[0];
    const float* adj = (const float*)d_in[1];
    const float* W1  = (const float*)d_in[2];
    const float* b1  = (const float*)d_in[3];
    const float* g1  = (const float*)d_in[4];
    const float* be1 = (const float*)d_in[5];
    const float* W2  = (const float*)d_in[6];
    const float* b2  = (const float*)d_in[7];
    const float* g2  = (const float*)d_in[8];
    const float* be2 = (const float*)d_in[9];
    float* out = (float*)d_out;

    float *dvec, *bufA, *bufB;
    cudaGetSymbolAddress((void**)&dvec, g_dvec);
    cudaGetSymbolAddress((void**)&bufA, g_bufA);
    cudaGetSymbolAddress((void**)&bufB, g_bufB);

    cudaFuncSetAttribute(gemm_tf32_kernel,
                         cudaFuncAttributeMaxDynamicSharedMemorySize, GEMM_SMEM);

    dim3 tgrid(FEAT / 32, NNODES / 32);      // (8, 256)
    dim3 tblock(32, 8);
    dim3 ggrid(FEAT / 128, NNODES / 128);    // (2, 64)
    dim3 sgrid(FEAT / 64, NNODES / 128);     // (4, 64)

    deg_kernel<<<NNODES, 256>>>(adj, dvec);

    // ---- layer 1 ----
    transpose_scale_kernel<<<tgrid, tblock>>>(x, dvec, bufA);
    gemm_tf32_kernel<<<ggrid, 128, GEMM_SMEM>>>(adj, bufA, dvec, bufB);
    gemm_nt_bias_kernel<<<sgrid, 128>>>(bufB, W1, b1, bufA);
    ln_gelu_kernel<<<NNODES, 256>>>(bufA, g1, be1, nullptr, bufB);

    // ---- layer 2 ----
    transpose_scale_kernel<<<tgrid, tblock>>>(bufB, dvec, bufA);
    gemm_tf32_kernel<<<ggrid, 128, GEMM_SMEM>>>(adj, bufA, dvec, bufB);
    gemm_nt_bias_kernel<<<sgrid, 128>>>(bufB, W2, b2, bufA);
    ln_gelu_kernel<<<NNODES, 256>>>(bufA, g2, be2, x, out);
}

// round 5
// speedup vs baseline: 3.8558x; 1.0429x over previous
#include <cuda_runtime.h>
#include <math.h>
#include <stdint.h>

// ---------------------------------------------------------------------------
// MultiLayerGNN: out = L2(L1(x)) + x
//   adj_norm @ v == d ⊙ (adj @ (d ⊙ v)),  d = rsqrt(max(rowsum(adj),1e-6))
// All 4 GEMMs on mma.sync tf32 (portable sm_80+ tensor path).
// Big GEMM: 256 threads, 2x2 spatial warps x 2 k-groups (intra-CTA split-K),
// 4-stage cp.async pipeline with a single __syncthreads per iteration.
// ---------------------------------------------------------------------------

#define NNODES 8192
#define FEAT   256

__device__ float g_dvec[NNODES];
__device__ float g_bufA[NNODES * FEAT];   // also holds Bt [256 x 8192]
__device__ float g_bufB[NNODES * FEAT];

// ---------------------------------------------------------------------------
__device__ __forceinline__ uint32_t smem_u32(const void* p) {
    uint32_t a;
    asm("{ .reg .u64 t; cvta.to.shared.u64 t, %1; cvt.u32.u64 %0, t; }"
        : "=r"(a) : "l"(p));
    return a;
}
__device__ __forceinline__ void cp_async16(uint32_t dst, const void* src) {
    asm volatile("cp.async.cg.shared.global [%0], [%1], 16;" :: "r"(dst), "l"(src) : "memory");
}
#define CP_COMMIT()  asm volatile("cp.async.commit_group;" ::: "memory")
#define CP_WAIT(n)   asm volatile("cp.async.wait_group %0;" :: "n"(n) : "memory")

__device__ __forceinline__ void mma_tf32_16x8x8(float* d, const uint32_t* a,
                                                const uint32_t* b) {
    asm volatile(
        "mma.sync.aligned.m16n8k8.row.col.f32.tf32.tf32.f32 "
        "{%0,%1,%2,%3}, {%4,%5,%6,%7}, {%8,%9}, {%0,%1,%2,%3};"
        : "+f"(d[0]), "+f"(d[1]), "+f"(d[2]), "+f"(d[3])
        : "r"(a[0]), "r"(a[1]), "r"(a[2]), "r"(a[3]), "r"(b[0]), "r"(b[1]));
}

// ---------------------------------------------------------------------------
__device__ __forceinline__ float block_sum_256(float v, float* sh8) {
    int t = threadIdx.x;
#pragma unroll
    for (int o = 16; o > 0; o >>= 1) v += __shfl_xor_sync(0xffffffffu, v, o);
    if ((t & 31) == 0) sh8[t >> 5] = v;
    __syncthreads();
    float tot = ((sh8[0] + sh8[1]) + (sh8[2] + sh8[3])) +
                ((sh8[4] + sh8[5]) + (sh8[6] + sh8[7]));
    __syncthreads();
    return tot;
}

// ---------------------------------------------------------------------------
// K1: d[i] = rsqrt(max(rowsum(adj), 1e-6))
// ---------------------------------------------------------------------------
__global__ void deg_kernel(const float* __restrict__ adj, float* __restrict__ d) {
    __shared__ float sh8[8];
    int row = blockIdx.x;
    int t = threadIdx.x;
    const float4* p = reinterpret_cast<const float4*>(adj + (size_t)row * NNODES);
    float s = 0.f;
#pragma unroll
    for (int i = 0; i < 8; i++) {
        float4 v = p[t + (i << 8)];
        s += (v.x + v.y) + (v.z + v.w);
    }
    float tot = block_sum_256(s, sh8);
    if (t == 0) d[row] = rsqrtf(fmaxf(tot, 1e-6f));
}

// ---------------------------------------------------------------------------
// K2: Bt[n, k] = d[k] * in[k, n]   ([8192,256] -> [256,8192])
// ---------------------------------------------------------------------------
__global__ void transpose_scale_kernel(const float* __restrict__ in,
                                       const float* __restrict__ d,
                                       float* __restrict__ out) {
    __shared__ float tile[32][33];
    int n0 = blockIdx.x * 32, k0 = blockIdx.y * 32;
    int tx = threadIdx.x, ty = threadIdx.y;
#pragma unroll
    for (int j = 0; j < 32; j += 8) {
        int k = k0 + ty + j;
        tile[ty + j][tx] = in[(size_t)k * FEAT + n0 + tx] * d[k];
    }
    __syncthreads();
#pragma unroll
    for (int j = 0; j < 32; j += 8) {
        int n = n0 + ty + j;
        out[(size_t)n * NNODES + k0 + tx] = tile[tx][ty + j];
    }
}

// ---------------------------------------------------------------------------
// K3: GEMM on mma.sync tf32.
//   BIAS=false: C[m,n] = aux[m] * sum_k A[m,k] * Bt[n,k]      (aux = dscale)
//   BIAS=true : C[m,n] = sum_k A[m,k] * Bt[n,k] + aux[n]      (aux = bias)
//   A: [M x KDIM] row-major; Bt: [256 x KDIM] row-major (= col-major B).
//   BM=BN=128, BK=32; 256 threads = 2x2 spatial warps x 2 k-groups.
//   Each k-group accumulates half of every BK block (kk = 2*wk + kx).
//   Cross-k reduction via SMEM at the end.
//   4-stage cp.async pipeline, one __syncthreads per mainloop iteration.
// ---------------------------------------------------------------------------
#define BK 32
#define ROWF 36                       // padded row stride (floats)
#define ROWB (ROWF * 4)               // 144 bytes
#define STG_F (128 * ROWF * 2)        // floats per stage (A+B) = 9216
#define STG_B (STG_F * 4)             // 36864 bytes
#define B_OFF_F (128 * ROWF)          // 4608
#define NSTAGE 4
#define GEMM_SMEM (NSTAGE * STG_B)    // 147456
#define REDSTRIDE 130                 // reduction tile row stride (floats)

template<int KDIM>
__device__ __forceinline__ void load_stage(uint32_t sb, int s, int k0,
                                           const float* A, const float* Bt,
                                           int br, int bc, int tid) {
    uint32_t ab = sb + s * STG_B;
    uint32_t bb = ab + B_OFF_F * 4;
#pragma unroll
    for (int j = 0; j < 4; j++) {
        int idx = tid + (j << 8);     // 0..1023
        int r = idx >> 3;             // 0..127
        int cs = (idx & 7) << 4;      // byte col 0..112
        cp_async16(ab + r * ROWB + cs,
                   (const char*)(A + (size_t)(br + r) * KDIM + k0) + cs);
    }
#pragma unroll
    for (int j = 0; j < 4; j++) {
        int idx = tid + (j << 8);
        int r = idx >> 3;
        int cs = (idx & 7) << 4;
        cp_async16(bb + r * ROWB + cs,
                   (const char*)(Bt + (size_t)(bc + r) * KDIM + k0) + cs);
    }
}

template<int KDIM, bool BIAS>
__global__ void __launch_bounds__(256, 1)
gemm_tf32_kernel(const float* __restrict__ A, const float* __restrict__ Bt,
                 const float* __restrict__ aux, float* __restrict__ C) {
    constexpr int NITER = KDIM / BK;
    extern __shared__ float smem_f[];
    uint32_t sb = smem_u32(smem_f);
    int tid = threadIdx.x;
    int wid = tid >> 5, lane = tid & 31;
    int r = lane >> 2, c = lane & 3;
    int wm = (wid & 1) << 6;          // warp row offset 0/64
    int wn = ((wid >> 1) & 1) << 6;   // warp col offset 0/64
    int wk = wid >> 2;                // k-group 0/1
    int br = blockIdx.y << 7, bc = blockIdx.x << 7;

    float acc[4][8][4];
#pragma unroll
    for (int i = 0; i < 4; i++)
#pragma unroll
        for (int j = 0; j < 8; j++)
#pragma unroll
            for (int q = 0; q < 4; q++) acc[i][j][q] = 0.f;

    // prologue: fill NSTAGE-1 stages
#pragma unroll
    for (int s = 0; s < NSTAGE - 1; s++) {
        load_stage<KDIM>(sb, s, s * BK, A, Bt, br, bc, tid);
        CP_COMMIT();
    }

    for (int it = 0; it < NITER; it++) {
        CP_WAIT(NSTAGE - 2);
        __syncthreads();                // stage it%4 ready for all warps;
                                        // also: all warps done with stage (it+3)%4
        int nk = it + NSTAGE - 1;
        if (nk < NITER)
            load_stage<KDIM>(sb, nk & 3, nk * BK, A, Bt, br, bc, tid);
        CP_COMMIT();

        const float* As = smem_f + (it & 3) * STG_F;
        const float* Bs = As + B_OFF_F;
#pragma unroll
        for (int kx = 0; kx < 2; kx++) {
            int kc = (((wk << 1) + kx) << 3) + c;
            uint32_t a[4][4], b[8][2];
#pragma unroll
            for (int i = 0; i < 4; i++) {
                int row = wm + (i << 4) + r;
                a[i][0] = __float_as_uint(As[row * ROWF + kc]);
                a[i][1] = __float_as_uint(As[(row + 8) * ROWF + kc]);
                a[i][2] = __float_as_uint(As[row * ROWF + kc + 4]);
                a[i][3] = __float_as_uint(As[(row + 8) * ROWF + kc + 4]);
            }
#pragma unroll
            for (int j = 0; j < 8; j++) {
                int col = wn + (j << 3) + r;
                b[j][0] = __float_as_uint(Bs[col * ROWF + kc]);
                b[j][1] = __float_as_uint(Bs[col * ROWF + kc + 4]);
            }
#pragma unroll
            for (int i = 0; i < 4; i++)
#pragma unroll
                for (int j = 0; j < 8; j++)
                    mma_tf32_16x8x8(acc[i][j], a[i], b[j]);
        }
    }

    // ---- cross-k reduction via SMEM (reuse stage memory) ----
    __syncthreads();                    // all compute done; safe to overwrite
    float* S = smem_f;
    if (wk == 1) {
#pragma unroll
        for (int i = 0; i < 4; i++) {
            int row = wm + (i << 4) + r;
#pragma unroll
            for (int j = 0; j < 8; j++) {
                int col = wn + (j << 3) + (c << 1);
                *reinterpret_cast<float2*>(&S[row * REDSTRIDE + col]) =
                    make_float2(acc[i][j][0], acc[i][j][1]);
                *reinterpret_cast<float2*>(&S[(row + 8) * REDSTRIDE + col]) =
                    make_float2(acc[i][j][2], acc[i][j][3]);
            }
        }
    }
    __syncthreads();
    if (wk == 0) {
#pragma unroll
        for (int i = 0; i < 4; i++) {
            int rloc = wm + (i << 4) + r;
            int row0 = br + rloc;
            float sc0 = 1.f, sc8 = 1.f;
            if (!BIAS) { sc0 = aux[row0]; sc8 = aux[row0 + 8]; }
#pragma unroll
            for (int j = 0; j < 8; j++) {
                int cloc = wn + (j << 3) + (c << 1);
                float2 p0 = *reinterpret_cast<float2*>(&S[rloc * REDSTRIDE + cloc]);
                float2 p8 = *reinterpret_cast<float2*>(&S[(rloc + 8) * REDSTRIDE + cloc]);
                float v00 = acc[i][j][0] + p0.x;
                float v01 = acc[i][j][1] + p0.y;
                float v80 = acc[i][j][2] + p8.x;
                float v81 = acc[i][j][3] + p8.y;
                if (BIAS) {
                    float bz0 = aux[bc + cloc];
                    float bz1 = aux[bc + cloc + 1];
                    v00 += bz0; v01 += bz1; v80 += bz0; v81 += bz1;
                } else {
                    v00 *= sc0; v01 *= sc0; v80 *= sc8; v81 *= sc8;
                }
                *reinterpret_cast<float2*>(&C[(size_t)row0 * FEAT + bc + cloc]) =
                    make_float2(v00, v01);
                *reinterpret_cast<float2*>(&C[(size_t)(row0 + 8) * FEAT + bc + cloc]) =
                    make_float2(v80, v81);
            }
        }
    }
}

// ---------------------------------------------------------------------------
// K5: out = gelu(LN(Z)) (+res)
// ---------------------------------------------------------------------------
__global__ void ln_gelu_kernel(const float* __restrict__ Z,
                               const float* __restrict__ g,
                               const float* __restrict__ beta,
                               const float* __restrict__ res,
                               float* __restrict__ out) {
    __shared__ float sh8[8];
    int row = blockIdx.x;
    int t = threadIdx.x;
    size_t idx = (size_t)row * FEAT + t;
    float v = Z[idx];
    float mean = block_sum_256(v, sh8) * (1.f / FEAT);
    float dv = v - mean;
    float var = block_sum_256(dv * dv, sh8) * (1.f / FEAT);
    float y = dv * rsqrtf(var + 1e-5f) * g[t] + beta[t];
    float rr = 0.5f * y * (1.f + erff(y * 0.70710678118654752f));
    if (res) rr += res[idx];
    out[idx] = rr;
}

// ---------------------------------------------------------------------------
// Launch: 9 kernels, graph-capturable, allocation-free.
// ---------------------------------------------------------------------------
extern "C" void kernel_launch(void* const* d_in, const int* in_sizes, int n_in,
                              void* d_out, int out_size) {
    const float* x   = (const float*)d_in[0];
    const float* adj = (const float*)d_in[1];
    const float* W1  = (const float*)d_in[2];
    const float* b1  = (const float*)d_in[3];
    const float* g1  = (const float*)d_in[4];
    const float* be1 = (const float*)d_in[5];
    const float* W2  = (const float*)d_in[6];
    const float* b2  = (const float*)d_in[7];
    const float* g2  = (const float*)d_in[8];
    const float* be2 = (const float*)d_in[9];
    float* out = (float*)d_out;

    float *dvec, *bufA, *bufB;
    cudaGetSymbolAddress((void**)&dvec, g_dvec);
    cudaGetSymbolAddress((void**)&bufA, g_bufA);
    cudaGetSymbolAddress((void**)&bufB, g_bufB);

    cudaFuncSetAttribute(gemm_tf32_kernel<NNODES, false>,
                         cudaFuncAttributeMaxDynamicSharedMemorySize, GEMM_SMEM);
    cudaFuncSetAttribute(gemm_tf32_kernel<FEAT, true>,
                         cudaFuncAttributeMaxDynamicSharedMemorySize, GEMM_SMEM);

    dim3 tgrid(FEAT / 32, NNODES / 32);      // (8, 256)
    dim3 tblock(32, 8);
    dim3 ggrid(FEAT / 128, NNODES / 128);    // (2, 64)

    deg_kernel<<<NNODES, 256>>>(adj, dvec);

    // ---- layer 1 ----
    transpose_scale_kernel<<<tgrid, tblock>>>(x, dvec, bufA);
    gemm_tf32_kernel<NNODES, false><<<ggrid, 256, GEMM_SMEM>>>(adj, bufA, dvec, bufB);
    gemm_tf32_kernel<FEAT, true><<<ggrid, 256, GEMM_SMEM>>>(bufB, W1, b1, bufA);
    ln_gelu_kernel<<<NNODES, 256>>>(bufA, g1, be1, nullptr, bufB);

    // ---- layer 2 ----
    transpose_scale_kernel<<<tgrid, tblock>>>(bufB, dvec, bufA);
    gemm_tf32_kernel<NNODES, false><<<ggrid, 256, GEMM_SMEM>>>(adj, bufA, dvec, bufB);
    gemm_tf32_kernel<FEAT, true><<<ggrid, 256, GEMM_SMEM>>>(bufB, W2, b2, bufA);
    ln_gelu_kernel<<<NNODES, 256>>>(bufA, g2, be2, x, out);
}

// round 8
// speedup vs baseline: 3.8709x; 1.0039x over previous
#include <cuda_runtime.h>
#include <math.h>
#include <stdint.h>

// ---------------------------------------------------------------------------
// MultiLayerGNN: out = L2(L1(x)) + x
//   adj_norm @ v == d ⊙ (adj @ (d ⊙ v)),  d = rsqrt(max(rowsum(adj),1e-6))
// All 4 GEMMs on mma.sync tf32; fragments loaded via ldmatrix.m8n8.x4.b16
// (the standard tf32 trick: each tf32 frag = 8x16B rows, conflict-free here).
// ---------------------------------------------------------------------------

#define NNODES 8192
#define FEAT   256

__device__ float g_dvec[NNODES];
__device__ float g_bufA[NNODES * FEAT];   // also holds Bt [256 x 8192]
__device__ float g_bufB[NNODES * FEAT];

// ---------------------------------------------------------------------------
__device__ __forceinline__ uint32_t smem_u32(const void* p) {
    uint32_t a;
    asm("{ .reg .u64 t; cvta.to.shared.u64 t, %1; cvt.u32.u64 %0, t; }"
        : "=r"(a) : "l"(p));
    return a;
}
__device__ __forceinline__ void cp_async16(uint32_t dst, const void* src) {
    asm volatile("cp.async.cg.shared.global [%0], [%1], 16;" :: "r"(dst), "l"(src) : "memory");
}
#define CP_COMMIT()  asm volatile("cp.async.commit_group;" ::: "memory")
#define CP_WAIT(n)   asm volatile("cp.async.wait_group %0;" :: "n"(n) : "memory")

__device__ __forceinline__ void ldmatrix_x4(uint32_t& r0, uint32_t& r1,
                                            uint32_t& r2, uint32_t& r3,
                                            uint32_t addr) {
    asm volatile("ldmatrix.sync.aligned.m8n8.x4.shared.b16 {%0,%1,%2,%3}, [%4];"
                 : "=r"(r0), "=r"(r1), "=r"(r2), "=r"(r3) : "r"(addr));
}

__device__ __forceinline__ void mma_tf32_16x8x8(float* d, const uint32_t* a,
                                                const uint32_t* b) {
    asm volatile(
        "mma.sync.aligned.m16n8k8.row.col.f32.tf32.tf32.f32 "
        "{%0,%1,%2,%3}, {%4,%5,%6,%7}, {%8,%9}, {%0,%1,%2,%3};"
        : "+f"(d[0]), "+f"(d[1]), "+f"(d[2]), "+f"(d[3])
        : "r"(a[0]), "r"(a[1]), "r"(a[2]), "r"(a[3]), "r"(b[0]), "r"(b[1]));
}

// ---------------------------------------------------------------------------
__device__ __forceinline__ float block_sum_256(float v, float* sh8) {
    int t = threadIdx.x;
#pragma unroll
    for (int o = 16; o > 0; o >>= 1) v += __shfl_xor_sync(0xffffffffu, v, o);
    if ((t & 31) == 0) sh8[t >> 5] = v;
    __syncthreads();
    float tot = ((sh8[0] + sh8[1]) + (sh8[2] + sh8[3])) +
                ((sh8[4] + sh8[5]) + (sh8[6] + sh8[7]));
    __syncthreads();
    return tot;
}

// ---------------------------------------------------------------------------
// K1: d[i] = rsqrt(max(rowsum(adj), 1e-6))
// ---------------------------------------------------------------------------
__global__ void deg_kernel(const float* __restrict__ adj, float* __restrict__ d) {
    __shared__ float sh8[8];
    int row = blockIdx.x;
    int t = threadIdx.x;
    const float4* p = reinterpret_cast<const float4*>(adj + (size_t)row * NNODES);
    float s = 0.f;
#pragma unroll
    for (int i = 0; i < 8; i++) {
        float4 v = p[t + (i << 8)];
        s += (v.x + v.y) + (v.z + v.w);
    }
    float tot = block_sum_256(s, sh8);
    if (t == 0) d[row] = rsqrtf(fmaxf(tot, 1e-6f));
}

// ---------------------------------------------------------------------------
// K2: Bt[n, k] = d[k] * in[k, n]   ([8192,256] -> [256,8192])
// ---------------------------------------------------------------------------
__global__ void transpose_scale_kernel(const float* __restrict__ in,
                                       const float* __restrict__ d,
                                       float* __restrict__ out) {
    __shared__ float tile[32][33];
    int n0 = blockIdx.x * 32, k0 = blockIdx.y * 32;
    int tx = threadIdx.x, ty = threadIdx.y;
#pragma unroll
    for (int j = 0; j < 32; j += 8) {
        int k = k0 + ty + j;
        tile[ty + j][tx] = in[(size_t)k * FEAT + n0 + tx] * d[k];
    }
    __syncthreads();
#pragma unroll
    for (int j = 0; j < 32; j += 8) {
        int n = n0 + ty + j;
        out[(size_t)n * NNODES + k0 + tx] = tile[tx][ty + j];
    }
}

// ---------------------------------------------------------------------------
// K3: GEMM on mma.sync tf32, ldmatrix fragment loads.
//   BIAS=false: C[m,n] = aux[m] * sum_k A[m,k] * Bt[n,k]      (aux = dscale)
//   BIAS=true : C[m,n] = sum_k A[m,k] * Bt[n,k] + aux[n]      (aux = bias)
//   BM=BN=128, BK=32; 256 threads = 2x2 spatial warps x 2 k-groups.
//   4-stage cp.async pipeline, one __syncthreads per mainloop iteration.
// ---------------------------------------------------------------------------
#define BK 32
#define ROWF 36                       // padded row stride (floats); 9x16B -> ldmatrix conflict-free
#define ROWB (ROWF * 4)               // 144 bytes
#define STG_F (128 * ROWF * 2)        // floats per stage (A+B) = 9216
#define STG_B (STG_F * 4)             // 36864 bytes
#define B_OFF_F (128 * ROWF)          // 4608
#define NSTAGE 4
#define GEMM_SMEM (NSTAGE * STG_B)    // 147456
#define REDSTRIDE 130                 // reduction tile row stride (floats)

template<int KDIM>
__device__ __forceinline__ void load_stage(uint32_t sb, int s, int k0,
                                           const float* A, const float* Bt,
                                           int br, int bc, int tid) {
    uint32_t ab = sb + s * STG_B;
    uint32_t bb = ab + B_OFF_F * 4;
#pragma unroll
    for (int j = 0; j < 4; j++) {
        int idx = tid + (j << 8);     // 0..1023
        int r = idx >> 3;             // 0..127
        int cs = (idx & 7) << 4;      // byte col 0..112
        cp_async16(ab + r * ROWB + cs,
                   (const char*)(A + (size_t)(br + r) * KDIM + k0) + cs);
    }
#pragma unroll
    for (int j = 0; j < 4; j++) {
        int idx = tid + (j << 8);
        int r = idx >> 3;
        int cs = (idx & 7) << 4;
        cp_async16(bb + r * ROWB + cs,
                   (const char*)(Bt + (size_t)(bc + r) * KDIM + k0) + cs);
    }
}

template<int KDIM, bool BIAS>
__global__ void __launch_bounds__(256, 1)
gemm_tf32_kernel(const float* __restrict__ A, const float* __restrict__ Bt,
                 const float* __restrict__ aux, float* __restrict__ C) {
    constexpr int NITER = KDIM / BK;
    extern __shared__ float smem_f[];
    uint32_t sb = smem_u32(smem_f);
    int tid = threadIdx.x;
    int wid = tid >> 5, lane = tid & 31;
    int r = lane >> 2, c = lane & 3;
    int wm = (wid & 1) << 6;          // warp row offset 0/64
    int wn = ((wid >> 1) & 1) << 6;   // warp col offset 0/64
    int wk = wid >> 2;                // k-group 0/1
    int br = blockIdx.y << 7, bc = blockIdx.x << 7;

    // ldmatrix per-lane offsets (bytes, relative to tile base + k-step base)
    // A x4 covers {rows 0-7 klo, rows 8-15 klo, rows 0-7 khi, rows 8-15 khi}
    int arow = (lane & 7) + (((lane >> 3) & 1) << 3);   // 0..15
    int akoff = (lane >> 4) << 2;                       // 0 or 4 floats
    uint32_t a_lane_off = (uint32_t)(arow * ROWF + akoff) << 2;
    // B x4 covers {j0 klo, j0 khi, j1 klo, j1 khi}; lane m = lane>>3
    int bm = lane >> 3;
    int bn = ((bm >> 1) << 3) + (lane & 7);             // 0..15 within j-pair
    int bkoff = (bm & 1) << 2;
    uint32_t b_lane_off = (uint32_t)(bn * ROWF + bkoff) << 2;

    float acc[4][8][4];
#pragma unroll
    for (int i = 0; i < 4; i++)
#pragma unroll
        for (int j = 0; j < 8; j++)
#pragma unroll
            for (int q = 0; q < 4; q++) acc[i][j][q] = 0.f;

    // prologue: fill NSTAGE-1 stages
#pragma unroll
    for (int s = 0; s < NSTAGE - 1; s++) {
        load_stage<KDIM>(sb, s, s * BK, A, Bt, br, bc, tid);
        CP_COMMIT();
    }

    for (int it = 0; it < NITER; it++) {
        CP_WAIT(NSTAGE - 2);
        __syncthreads();                // stage it%4 ready; stage (it+3)%4 free
        int nk = it + NSTAGE - 1;
        if (nk < NITER)
            load_stage<KDIM>(sb, nk & 3, nk * BK, A, Bt, br, bc, tid);
        CP_COMMIT();

        uint32_t As = sb + (it & 3) * STG_B + ((uint32_t)(wm * ROWF) << 2);
        uint32_t Bs = sb + (it & 3) * STG_B + (B_OFF_F << 2) +
                      ((uint32_t)(wn * ROWF) << 2);
#pragma unroll
        for (int kx = 0; kx < 2; kx++) {
            uint32_t kb = ((uint32_t)(((wk << 1) + kx) << 3)) << 2;  // k-step byte off
            uint32_t a[4][4], b[8][2];
#pragma unroll
            for (int i = 0; i < 4; i++)
                ldmatrix_x4(a[i][0], a[i][1], a[i][2], a[i][3],
                            As + ((uint32_t)(i * 16 * ROWF) << 2) + kb + a_lane_off);
#pragma unroll
            for (int p = 0; p < 4; p++)
                ldmatrix_x4(b[2*p][0], b[2*p][1], b[2*p+1][0], b[2*p+1][1],
                            Bs + ((uint32_t)(p * 16 * ROWF) << 2) + kb + b_lane_off);
#pragma unroll
            for (int i = 0; i < 4; i++)
#pragma unroll
                for (int j = 0; j < 8; j++)
                    mma_tf32_16x8x8(acc[i][j], a[i], b[j]);
        }
    }

    // ---- cross-k reduction via SMEM (reuse stage memory) ----
    __syncthreads();                    // all compute done; safe to overwrite
    float* S = smem_f;
    if (wk == 1) {
#pragma unroll
        for (int i = 0; i < 4; i++) {
            int row = wm + (i << 4) + r;
#pragma unroll
            for (int j = 0; j < 8; j++) {
                int col = wn + (j << 3) + (c << 1);
                *reinterpret_cast<float2*>(&S[row * REDSTRIDE + col]) =
                    make_float2(acc[i][j][0], acc[i][j][1]);
                *reinterpret_cast<float2*>(&S[(row + 8) * REDSTRIDE + col]) =
                    make_float2(acc[i][j][2], acc[i][j][3]);
            }
        }
    }
    __syncthreads();
    if (wk == 0) {
#pragma unroll
        for (int i = 0; i < 4; i++) {
            int rloc = wm + (i << 4) + r;
            int row0 = br + rloc;
            float sc0 = 1.f, sc8 = 1.f;
            if (!BIAS) { sc0 = aux[row0]; sc8 = aux[row0 + 8]; }
#pragma unroll
            for (int j = 0; j < 8; j++) {
                int cloc = wn + (j << 3) + (c << 1);
                float2 p0 = *reinterpret_cast<float2*>(&S[rloc * REDSTRIDE + cloc]);
                float2 p8 = *reinterpret_cast<float2*>(&S[(rloc + 8) * REDSTRIDE + cloc]);
                float v00 = acc[i][j][0] + p0.x;
                float v01 = acc[i][j][1] + p0.y;
                float v80 = acc[i][j][2] + p8.x;
                float v81 = acc[i][j][3] + p8.y;
                if (BIAS) {
                    float bz0 = aux[bc + cloc];
                    float bz1 = aux[bc + cloc + 1];
                    v00 += bz0; v01 += bz1; v80 += bz0; v81 += bz1;
                } else {
                    v00 *= sc0; v01 *= sc0; v80 *= sc8; v81 *= sc8;
                }
                *reinterpret_cast<float2*>(&C[(size_t)row0 * FEAT + bc + cloc]) =
                    make_float2(v00, v01);
                *reinterpret_cast<float2*>(&C[(size_t)(row0 + 8) * FEAT + bc + cloc]) =
                    make_float2(v80, v81);
            }
        }
    }
}

// ---------------------------------------------------------------------------
// K5: out = gelu(LN(Z)) (+res)
// ---------------------------------------------------------------------------
__global__ void ln_gelu_kernel(const float* __restrict__ Z,
                               const float* __restrict__ g,
                               const float* __restrict__ beta,
                               const float* __restrict__ res,
                               float* __restrict__ out) {
    __shared__ float sh8[8];
    int row = blockIdx.x;
    int t = threadIdx.x;
    size_t idx = (size_t)row * FEAT + t;
    float v = Z[idx];
    float mean = block_sum_256(v, sh8) * (1.f / FEAT);
    float dv = v - mean;
    float var = block_sum_256(dv * dv, sh8) * (1.f / FEAT);
    float y = dv * rsqrtf(var + 1e-5f) * g[t] + beta[t];
    float rr = 0.5f * y * (1.f + erff(y * 0.70710678118654752f));
    if (res) rr += res[idx];
    out[idx] = rr;
}

// ---------------------------------------------------------------------------
// Launch: 9 kernels, graph-capturable, allocation-free.
// ---------------------------------------------------------------------------
extern "C" void kernel_launch(void* const* d_in, const int* in_sizes, int n_in,
                              void* d_out, int out_size) {
    const float* x   = (const float*)d_in[0];
    const float* adj = (const float*)d_in[1];
    const float* W1  = (const float*)d_in[2];
    const float* b1  = (const float*)d_in[3];
    const float* g1  = (const float*)d_in[4];
    const float* be1 = (const float*)d_in[5];
    const float* W2  = (const float*)d_in[6];
    const float* b2  = (const float*)d_in[7];
    const float* g2  = (const float*)d_in[8];
    const float* be2 = (const float*)d_in[9];
    float* out = (float*)d_out;

    float *dvec, *bufA, *bufB;
    cudaGetSymbolAddress((void**)&dvec, g_dvec);
    cudaGetSymbolAddress((void**)&bufA, g_bufA);
    cudaGetSymbolAddress((void**)&bufB, g_bufB);

    cudaFuncSetAttribute(gemm_tf32_kernel<NNODES, false>,
                         cudaFuncAttributeMaxDynamicSharedMemorySize, GEMM_SMEM);
    cudaFuncSetAttribute(gemm_tf32_kernel<FEAT, true>,
                         cudaFuncAttributeMaxDynamicSharedMemorySize, GEMM_SMEM);

    dim3 tgrid(FEAT / 32, NNODES / 32);      // (8, 256)
    dim3 tblock(32, 8);
    dim3 ggrid(FEAT / 128, NNODES / 128);    // (2, 64)

    deg_kernel<<<NNODES, 256>>>(adj, dvec);

    // ---- layer 1 ----
    transpose_scale_kernel<<<tgrid, tblock>>>(x, dvec, bufA);
    gemm_tf32_kernel<NNODES, false><<<ggrid, 256, GEMM_SMEM>>>(adj, bufA, dvec, bufB);
    gemm_tf32_kernel<FEAT, true><<<ggrid, 256, GEMM_SMEM>>>(bufB, W1, b1, bufA);
    ln_gelu_kernel<<<NNODES, 256>>>(bufA, g1, be1, nullptr, bufB);

    // ---- layer 2 ----
    transpose_scale_kernel<<<tgrid, tblock>>>(bufB, dvec, bufA);
    gemm_tf32_kernel<NNODES, false><<<ggrid, 256, GEMM_SMEM>>>(adj, bufA, dvec, bufB);
    gemm_tf32_kernel<FEAT, true><<<ggrid, 256, GEMM_SMEM>>>(bufB, W2, b2, bufA);
    ln_gelu_kernel<<<NNODES, 256>>>(bufA, g2, be2, x, out);
}